// round 16
// baseline (speedup 1.0000x reference)
#include <cuda_runtime.h>
#include <cuda_fp16.h>
#include <cstdint>

#define Bq    8
#define Nq    4096
#define Cq    1024
#define ICq   256
#define ROWS  (Bq * Nq)
#define EPSq  1e-5f

// ---------------------------------------------------------------------------
// Scratch (device globals)
// ---------------------------------------------------------------------------
__device__ __align__(256) __half  g_vh[ROWS * Cq];       // fp16 v; REUSED as fp16 W_y
__device__ __align__(256) __half  g_Ph[ROWS * 768];      // [G | Theta | Phi], ld=768
__device__ __align__(256) __half  g_wh[4 * ICq * Cq];
__device__ __align__(256) __half  g_Mh[Bq * ICq * ICq];
__device__ __align__(256) __half  g_Qh[Bq * Cq * ICq];
__device__ __align__(256) float   g_M[Bq * ICq * ICq];
__device__ __align__(256) float   g_bcat[768];
__device__ float g_sum[Cq];
__device__ float g_sumsq[Cq];

// ---------------------------------------------------------------------------
// Helpers
// ---------------------------------------------------------------------------
__device__ __forceinline__ uint32_t smem_u32(const void* p) {
    uint32_t a;
    asm("{ .reg .u64 t; cvta.to.shared.u64 t, %1; cvt.u32.u64 %0, t; }"
        : "=r"(a) : "l"(p));
    return a;
}

__device__ __forceinline__ void mma_h(float* c, const uint32_t* a, const uint32_t* b) {
    asm volatile(
        "mma.sync.aligned.m16n8k16.row.col.f32.f16.f16.f32 "
        "{%0,%1,%2,%3}, {%4,%5,%6,%7}, {%8,%9}, {%0,%1,%2,%3};"
        : "+f"(c[0]), "+f"(c[1]), "+f"(c[2]), "+f"(c[3])
        : "r"(a[0]), "r"(a[1]), "r"(a[2]), "r"(a[3]), "r"(b[0]), "r"(b[1]));
}

__device__ __forceinline__ void mma_t(float* c, const uint32_t* a, const uint32_t* b) {
    asm volatile(
        "mma.sync.aligned.m16n8k8.row.col.f32.tf32.tf32.f32 "
        "{%0,%1,%2,%3}, {%4,%5,%6,%7}, {%8,%9}, {%0,%1,%2,%3};"
        : "+f"(c[0]), "+f"(c[1]), "+f"(c[2]), "+f"(c[3])
        : "r"(a[0]), "r"(a[1]), "r"(a[2]), "r"(a[3]), "r"(b[0]), "r"(b[1]));
}

__device__ __forceinline__ uint32_t ldh_f32(uint32_t addr) {
    float f;
    asm("{\n\t.reg .f16 h;\n\tld.shared.b16 h, [%1];\n\tcvt.f32.f16 %0, h;\n\t}"
        : "=f"(f) : "r"(addr));
    return __float_as_uint(f);
}

#define LDM_X4(r0, r1, r2, r3, addr) \
    asm volatile("ldmatrix.sync.aligned.m8n8.x4.shared.b16 {%0,%1,%2,%3}, [%4];" \
                 : "=r"(r0), "=r"(r1), "=r"(r2), "=r"(r3) : "r"(addr))

#define CP_ASYNC(dst, src) \
    asm volatile("cp.async.cg.shared.global [%0], [%1], 16;" :: "r"(dst), "l"(src))
#define CP_COMMIT() asm volatile("cp.async.commit_group;" ::: "memory")
#define CP_WAIT1()  asm volatile("cp.async.wait_group 1;" ::: "memory")

// ---------------------------------------------------------------------------
// fp16 NT GEMM. Block 128x128, warp 64x32 (8 warps 2x4), BK=64 halves.
// RASTER: m0 = blockIdx.y, n0 = blockIdx.x  (x fastest -> consecutive CTAs
// share the A tile; A becomes L2-resident instead of re-streamed per N-block).
// smem rows [row][k] fp16, stride 144 B. ldmatrix frags. 3-stage cp.async.
// Stage = 36864 B; x3 = 110592 B. 2 CTA/SM.
// ---------------------------------------------------------------------------
#define TGH_STAGE_B  36864
#define TGH_BOFF     18432
#define TGH_SMEM     (3 * TGH_STAGE_B)

template<bool HOUT, bool STATS>
__global__ __launch_bounds__(256, 2)
void hgemm(const __half* __restrict__ A, int lda, long long sA,
           const __half* __restrict__ B, int ldb, long long sB,
           const float* __restrict__ bias,
           void* __restrict__ Cv, int ldC, long long sC,
           int K)
{
    extern __shared__ char smem[];
    const uint32_t sb = smem_u32(smem);

    const int tid  = threadIdx.x;
    const int lane = tid & 31;
    const int wid  = tid >> 5;
    const int wm   = wid & 1;
    const int wn   = wid >> 1;
    const int g    = lane >> 2;
    const int t    = lane & 3;

    A += (long long)blockIdx.z * sA;
    B += (long long)blockIdx.z * sB;
    const long long m0 = (long long)blockIdx.y * 128;   // swapped raster
    const long long n0 = (long long)blockIdx.x * 128;

    // cp.async mapping: s = tid + 256*i -> row = s>>3, c16 = s&7
    const __half* srcA[4];
    const __half* srcB[4];
    uint32_t dstO[4];
    #pragma unroll
    for (int i = 0; i < 4; i++) {
        int s = tid + 256 * i;
        int row = s >> 3, c16 = s & 7;
        srcA[i] = A + (m0 + row) * (long long)lda + c16 * 8;
        srcB[i] = B + (n0 + row) * (long long)ldb + c16 * 8;
        dstO[i] = (uint32_t)(row * 144 + c16 * 16);
    }

    // ldmatrix lane addressing (stride 144 B)
    const int tau = lane >> 3, r8 = lane & 7;
    uint32_t aoff[4], boff[2];
    #pragma unroll
    for (int mt = 0; mt < 4; mt++)
        aoff[mt] = (uint32_t)((wm * 64 + mt * 16 + ((tau & 1) << 3) + r8) * 144
                              + ((tau >> 1) << 4));
    #pragma unroll
    for (int np = 0; np < 2; np++)
        boff[np] = (uint32_t)(TGH_BOFF
                              + (wn * 32 + np * 16 + ((tau >> 1) << 3) + r8) * 144
                              + ((tau & 1) << 4));

    const int NCH = K >> 6;

#define TGH_LOAD(c, st) do {                              \
        uint32_t b_ = sb + (st) * TGH_STAGE_B;            \
        int k_ = (c) << 6;                                \
        _Pragma("unroll")                                 \
        for (int i_ = 0; i_ < 4; i_++) {                  \
            CP_ASYNC(b_ + dstO[i_],            srcA[i_] + k_); \
            CP_ASYNC(b_ + TGH_BOFF + dstO[i_], srcB[i_] + k_); \
        }                                                 \
    } while (0)

    TGH_LOAD(0, 0); CP_COMMIT();
    TGH_LOAD(1, 1); CP_COMMIT();

    float acc[4][4][4];
    #pragma unroll
    for (int a = 0; a < 4; a++)
        #pragma unroll
        for (int b = 0; b < 4; b++)
            #pragma unroll
            for (int q = 0; q < 4; q++) acc[a][b][q] = 0.f;

    for (int c = 0; c < NCH; ++c) {
        const uint32_t base = sb + (c % 3) * TGH_STAGE_B;
        CP_WAIT1();
        __syncthreads();
        if (c + 2 < NCH) { TGH_LOAD(c + 2, (c + 2) % 3); }
        CP_COMMIT();

        #pragma unroll
        for (int kg = 0; kg < 4; kg++) {
            const uint32_t kb = kg * 32;
            uint32_t af[4][4], bf[4][2];
            #pragma unroll
            for (int mt = 0; mt < 4; mt++)
                LDM_X4(af[mt][0], af[mt][1], af[mt][2], af[mt][3],
                       base + aoff[mt] + kb);
            #pragma unroll
            for (int np = 0; np < 2; np++)
                LDM_X4(bf[2 * np][0], bf[2 * np][1], bf[2 * np + 1][0], bf[2 * np + 1][1],
                       base + boff[np] + kb);
            #pragma unroll
            for (int mt = 0; mt < 4; mt++)
                #pragma unroll
                for (int nt = 0; nt < 4; nt++)
                    mma_h(acc[mt][nt], af[mt], bf[nt]);
        }
    }
#undef TGH_LOAD

    // ---- epilogue ----
    float* ssum = nullptr; float* ssq = nullptr;
    if (STATS) {
        __syncthreads();
        ssum = (float*)smem; ssq = ssum + 128;
        if (tid < 128) { ssum[tid] = 0.f; ssq[tid] = 0.f; }
        __syncthreads();
    }

    float colS[4][2], colS2[4][2];
    if (STATS) {
        #pragma unroll
        for (int nt = 0; nt < 4; nt++)
            colS[nt][0] = colS[nt][1] = colS2[nt][0] = colS2[nt][1] = 0.f;
    }

    #pragma unroll
    for (int mt = 0; mt < 4; mt++) {
        const long long row = m0 + wm * 64 + mt * 16 + g;
        #pragma unroll
        for (int nt = 0; nt < 4; nt++) {
            const long long col = n0 + wn * 32 + nt * 8 + 2 * t;
            const float b0 = bias ? __ldg(&bias[col])     : 0.f;
            const float b1 = bias ? __ldg(&bias[col + 1]) : 0.f;
            float v00 = acc[mt][nt][0] + b0, v01 = acc[mt][nt][1] + b1;
            float v10 = acc[mt][nt][2] + b0, v11 = acc[mt][nt][3] + b1;
            if (STATS) {
                colS[nt][0]  += v00 + v10;          colS[nt][1]  += v01 + v11;
                colS2[nt][0] += v00*v00 + v10*v10;  colS2[nt][1] += v01*v01 + v11*v11;
            }
            if (HOUT) {
                __half* Ch = (__half*)Cv + (long long)blockIdx.z * sC;
                *reinterpret_cast<__half2*>(&Ch[row * ldC + col]) =
                    __floats2half2_rn(v00, v01);
                *reinterpret_cast<__half2*>(&Ch[(row + 8) * ldC + col]) =
                    __floats2half2_rn(v10, v11);
            } else {
                float* Cf = (float*)Cv + (long long)blockIdx.z * sC;
                *reinterpret_cast<float2*>(&Cf[row * ldC + col]) = make_float2(v00, v01);
                *reinterpret_cast<float2*>(&Cf[(row + 8) * ldC + col]) = make_float2(v10, v11);
            }
        }
    }

    if (STATS) {
        #pragma unroll
        for (int nt = 0; nt < 4; nt++) {
            const int cl = wn * 32 + nt * 8 + 2 * t;
            atomicAdd(&ssum[cl],     colS[nt][0]);
            atomicAdd(&ssum[cl + 1], colS[nt][1]);
            atomicAdd(&ssq[cl],      colS2[nt][0]);
            atomicAdd(&ssq[cl + 1],  colS2[nt][1]);
        }
        __syncthreads();
        if (tid < 128) {
            atomicAdd(&g_sum[n0 + tid],   ssum[tid]);
            atomicAdd(&g_sumsq[n0 + tid], ssq[tid]);
        }
    }
}

// ---------------------------------------------------------------------------
// phiTg: M_b[i][j] = (1/N) sum_n Phi_b[n][i] * G_b[n][j]
// fp16 smem [k=n][i] stride 272 B; tf32 mma, exact f16->f32 fragments.
// Split-K: 8 chunks of 512 n; BK=16.
// ---------------------------------------------------------------------------
#define PH_STAGE_B 8704
#define PH_SMEM    (3 * PH_STAGE_B)
#define LDP 768

__global__ __launch_bounds__(256, 2)
void phiTg(const __half* __restrict__ P)
{
    extern __shared__ char smem[];
    const uint32_t sb = smem_u32(smem);

    const int tid  = threadIdx.x;
    const int lane = tid & 31;
    const int wid  = tid >> 5;
    const int wm   = wid & 1;
    const int wn   = wid >> 1;
    const int g    = lane >> 2;
    const int t    = lane & 3;

    const int batch = blockIdx.z >> 3;
    const int chunk = blockIdx.z & 7;
    const int i0 = blockIdx.x * 128;
    const int j0 = blockIdx.y * 128;

    const __half* Phi = P + 512;
    const __half* G   = P;
    const long long base = ((long long)batch * Nq + (long long)chunk * 512) * LDP;

    const int nr = tid >> 4, sg = tid & 15;
    const __half* srcP = Phi + base + (long long)nr * LDP + i0 + sg * 8;
    const __half* srcG = G   + base + (long long)nr * LDP + j0 + sg * 8;
    const uint32_t dst = nr * 272 + sg * 16;

    const int NCH = 32;

#define PH_LOAD(c, st) do {                          \
        uint32_t b_ = sb + (st) * PH_STAGE_B;        \
        long long k_ = (long long)(c) * 16 * LDP;    \
        CP_ASYNC(b_ + dst,        srcP + k_);        \
        CP_ASYNC(b_ + 4352 + dst, srcG + k_);        \
    } while (0)

    PH_LOAD(0, 0); CP_COMMIT();
    PH_LOAD(1, 1); CP_COMMIT();

    float acc[4][4][4];
    #pragma unroll
    for (int a = 0; a < 4; a++)
        #pragma unroll
        for (int b = 0; b < 4; b++)
            #pragma unroll
            for (int q = 0; q < 4; q++) acc[a][b][q] = 0.f;

    for (int c = 0; c < NCH; ++c) {
        const int st = c % 3;
        CP_WAIT1();
        __syncthreads();
        if (c + 2 < NCH) { PH_LOAD(c + 2, (c + 2) % 3); }
        CP_COMMIT();

        const uint32_t pA = sb + st * PH_STAGE_B;
        const uint32_t pB = pA + 4352;

        #pragma unroll
        for (int kk = 0; kk < 16; kk += 8) {
            uint32_t af[4][4], bf[4][2];
            #pragma unroll
            for (int mt = 0; mt < 4; mt++) {
                const int ir = wm * 64 + mt * 16 + g;
                af[mt][0] = ldh_f32(pA + ((kk + t) * 136 + ir) * 2);
                af[mt][1] = ldh_f32(pA + ((kk + t) * 136 + ir + 8) * 2);
                af[mt][2] = ldh_f32(pA + ((kk + t + 4) * 136 + ir) * 2);
                af[mt][3] = ldh_f32(pA + ((kk + t + 4) * 136 + ir + 8) * 2);
            }
            #pragma unroll
            for (int nt = 0; nt < 4; nt++) {
                const int jc = wn * 32 + nt * 8 + g;
                bf[nt][0] = ldh_f32(pB + ((kk + t) * 136 + jc) * 2);
                bf[nt][1] = ldh_f32(pB + ((kk + t + 4) * 136 + jc) * 2);
            }
            #pragma unroll
            for (int mt = 0; mt < 4; mt++)
                #pragma unroll
                for (int nt = 0; nt < 4; nt++)
                    mma_t(acc[mt][nt], af[mt], bf[nt]);
        }
    }
#undef PH_LOAD

    float* Mb = g_M + (long long)batch * ICq * ICq;
    const float scale = 1.f / (float)Nq;
    #pragma unroll
    for (int mt = 0; mt < 4; mt++) {
        const int row = i0 + wm * 64 + mt * 16 + g;
        #pragma unroll
        for (int nt = 0; nt < 4; nt++) {
            const int col = j0 + wn * 32 + nt * 8 + 2 * t;
            atomicAdd(&Mb[row * ICq + col],           acc[mt][nt][0] * scale);
            atomicAdd(&Mb[row * ICq + col + 1],       acc[mt][nt][1] * scale);
            atomicAdd(&Mb[(row + 8) * ICq + col],     acc[mt][nt][2] * scale);
            atomicAdd(&Mb[(row + 8) * ICq + col + 1], acc[mt][nt][3] * scale);
        }
    }
}

// ---------------------------------------------------------------------------
// Small kernels
// ---------------------------------------------------------------------------
__global__ __launch_bounds__(256)
void conv_f2h(const float4* __restrict__ src, __half2* __restrict__ dst, int n4)
{
    int i = blockIdx.x * 256 + threadIdx.x;
    if (i < n4) {
        float4 x = src[i];
        dst[2 * i]     = __floats2half2_rn(x.x, x.y);
        dst[2 * i + 1] = __floats2half2_rn(x.z, x.w);
    }
}

__global__ void prep_misc(const float* gb, const float* tb, const float* pb)
{
    int i = blockIdx.x * blockDim.x + threadIdx.x;
    if (i < Bq * ICq * ICq) g_M[i] = 0.f;
    if (i < Cq) { g_sum[i] = 0.f; g_sumsq[i] = 0.f; }
    if (i < ICq) {
        g_bcat[i]       = gb[i];
        g_bcat[i + 256] = tb[i];
        g_bcat[i + 512] = pb[i];
    }
}

// out = (Wy_h - mean)*rsqrt(var+eps)*gamma + beta + v
__global__ __launch_bounds__(256)
void bn_finalize(float* __restrict__ out, const __half2* __restrict__ wy,
                 const float* __restrict__ v,
                 const float* __restrict__ gamma, const float* __restrict__ beta)
{
    const long long i4 = (long long)blockIdx.x * 256 + threadIdx.x;
    const int c4 = (int)(i4 & (Cq / 4 - 1)) * 4;
    float2 a = __half22float2(wy[2 * i4]);
    float2 b = __half22float2(wy[2 * i4 + 1]);
    float4 vv = reinterpret_cast<const float4*>(v)[i4];
    const float inv = 1.f / (float)ROWS;
    float w4[4] = {a.x, a.y, b.x, b.y};
    const float* vp = &vv.x;
    float4 o;
    float* op = &o.x;
    #pragma unroll
    for (int c = 0; c < 4; c++) {
        float mean = g_sum[c4 + c] * inv;
        float var  = g_sumsq[c4 + c] * inv - mean * mean;
        float sc   = gamma[c4 + c] * rsqrtf(var + EPSq);
        op[c] = (w4[c] - mean) * sc + beta[c4 + c] + vp[c];
    }
    reinterpret_cast<float4*>(out)[i4] = o;
}

// ---------------------------------------------------------------------------
// Launch
// ---------------------------------------------------------------------------
extern "C" void kernel_launch(void* const* d_in, const int* in_sizes, int n_in,
                              void* d_out, int out_size)
{
    const float* v     = (const float*)d_in[0];
    const float* g_w   = (const float*)d_in[1];
    const float* g_b   = (const float*)d_in[2];
    const float* th_w  = (const float*)d_in[3];
    const float* th_b  = (const float*)d_in[4];
    const float* ph_w  = (const float*)d_in[5];
    const float* ph_b  = (const float*)d_in[6];
    const float* W_w   = (const float*)d_in[7];
    const float* W_b   = (const float*)d_in[8];
    const float* gamma = (const float*)d_in[9];
    const float* beta  = (const float*)d_in[10];
    float* out = (float*)d_out;

    __half *vh, *Ph, *wh, *Mh, *Qh;
    float *M, *bcat;
    cudaGetSymbolAddress((void**)&vh,   g_vh);
    cudaGetSymbolAddress((void**)&Ph,   g_Ph);
    cudaGetSymbolAddress((void**)&wh,   g_wh);
    cudaGetSymbolAddress((void**)&Mh,   g_Mh);
    cudaGetSymbolAddress((void**)&Qh,   g_Qh);
    cudaGetSymbolAddress((void**)&M,    g_M);
    cudaGetSymbolAddress((void**)&bcat, g_bcat);

    cudaFuncSetAttribute(hgemm<true, false>,
                         cudaFuncAttributeMaxDynamicSharedMemorySize, TGH_SMEM);
    cudaFuncSetAttribute(hgemm<true, true>,
                         cudaFuncAttributeMaxDynamicSharedMemorySize, TGH_SMEM);
    cudaFuncSetAttribute(phiTg,
                         cudaFuncAttributeMaxDynamicSharedMemorySize, PH_SMEM);

    const int WK = ICq * Cq;

    prep_misc<<<(Bq * ICq * ICq + 255) / 256, 256>>>(g_b, th_b, ph_b);

    conv_f2h<<<(ROWS * Cq / 4 + 255) / 256, 256>>>((const float4*)v, (__half2*)vh, ROWS * Cq / 4);
    conv_f2h<<<(WK / 4 + 255) / 256, 256>>>((const float4*)g_w,  (__half2*)(wh + 0 * WK), WK / 4);
    conv_f2h<<<(WK / 4 + 255) / 256, 256>>>((const float4*)th_w, (__half2*)(wh + 1 * WK), WK / 4);
    conv_f2h<<<(WK / 4 + 255) / 256, 256>>>((const float4*)ph_w, (__half2*)(wh + 2 * WK), WK / 4);
    conv_f2h<<<(WK / 4 + 255) / 256, 256>>>((const float4*)W_w,  (__half2*)(wh + 3 * WK), WK / 4);

    // 1. Fused projections: P = vh @ [g;th;ph]^T + bcat  (32768 x 768, K=1024)
    //    grid = (N-tiles, M-tiles): x-fastest shares the A (vh) tile in L2.
    {
        dim3 grid(768 / 128, ROWS / 128, 1);     // (6, 256)
        hgemm<true, false><<<grid, 256, TGH_SMEM>>>(
            vh, Cq, 0LL, wh, Cq, 0LL, bcat, Ph, 768, 0LL, Cq);
    }

    // 2. M_b = Phi_b^T G_b / N, convert to fp16
    {
        dim3 grid(ICq / 128, ICq / 128, Bq * 8);
        phiTg<<<grid, 256, PH_SMEM>>>(Ph);
        conv_f2h<<<(Bq * ICq * ICq / 4 + 255) / 256, 256>>>(
            (const float4*)M, (__half2*)Mh, Bq * ICq * ICq / 4);
    }

    // 3. Q_b = W_w @ M_b^T  (1024 x 256, K=256)
    {
        dim3 grid(ICq / 128, Cq / 128, Bq);      // (2, 8, 8)
        hgemm<true, false><<<grid, 256, TGH_SMEM>>>(
            wh + 3 * WK, ICq, 0LL,
            Mh, ICq, (long long)ICq * ICq,
            nullptr,
            Qh, ICq, (long long)Cq * ICq,
            ICq);
    }

    // 4. W_y = Theta_b @ Q_b^T + W_b  (fp16 out into vh) + BN stats
    {
        dim3 grid(Cq / 128, Nq / 128, Bq);       // (8, 32, 8)
        hgemm<true, true><<<grid, 256, TGH_SMEM>>>(
            Ph + 256, 768, (long long)Nq * 768,
            Qh, ICq, (long long)Cq * ICq,
            W_b,
            vh, Cq, (long long)Nq * Cq,
            ICq);
    }

    // 5. normalize + residual (reads fp16 W_y + fp32 v)
    bn_finalize<<<(ROWS * Cq / 4) / 256, 256>>>(
        out, (const __half2*)vh, v, gamma, beta);
}

// round 17
// speedup vs baseline: 1.0053x; 1.0053x over previous
#include <cuda_runtime.h>
#include <cuda_fp16.h>
#include <cstdint>

#define Bq    8
#define Nq    4096
#define Cq    1024
#define ICq   256
#define ROWS  (Bq * Nq)
#define EPSq  1e-5f

// ---------------------------------------------------------------------------
// Scratch (device globals)
// ---------------------------------------------------------------------------
__device__ __align__(256) __half  g_vh[ROWS * Cq];       // fp16 v; REUSED as fp16 W_y
__device__ __align__(256) __half  g_Ph[ROWS * 768];      // [G | Theta | Phi], ld=768
__device__ __align__(256) __half  g_wh[4 * ICq * Cq];
__device__ __align__(256) __half  g_Mh[Bq * ICq * ICq];
__device__ __align__(256) __half  g_Qh[Bq * Cq * ICq];
__device__ __align__(256) float   g_M[Bq * ICq * ICq];
__device__ __align__(256) float   g_bcat[768];
__device__ float g_sum[Cq];
__device__ float g_sumsq[Cq];

// ---------------------------------------------------------------------------
// Helpers
// ---------------------------------------------------------------------------
__device__ __forceinline__ uint32_t smem_u32(const void* p) {
    uint32_t a;
    asm("{ .reg .u64 t; cvta.to.shared.u64 t, %1; cvt.u32.u64 %0, t; }"
        : "=r"(a) : "l"(p));
    return a;
}

__device__ __forceinline__ void mma_h(float* c, const uint32_t* a, const uint32_t* b) {
    asm volatile(
        "mma.sync.aligned.m16n8k16.row.col.f32.f16.f16.f32 "
        "{%0,%1,%2,%3}, {%4,%5,%6,%7}, {%8,%9}, {%0,%1,%2,%3};"
        : "+f"(c[0]), "+f"(c[1]), "+f"(c[2]), "+f"(c[3])
        : "r"(a[0]), "r"(a[1]), "r"(a[2]), "r"(a[3]), "r"(b[0]), "r"(b[1]));
}

__device__ __forceinline__ void mma_t(float* c, const uint32_t* a, const uint32_t* b) {
    asm volatile(
        "mma.sync.aligned.m16n8k8.row.col.f32.tf32.tf32.f32 "
        "{%0,%1,%2,%3}, {%4,%5,%6,%7}, {%8,%9}, {%0,%1,%2,%3};"
        : "+f"(c[0]), "+f"(c[1]), "+f"(c[2]), "+f"(c[3])
        : "r"(a[0]), "r"(a[1]), "r"(a[2]), "r"(a[3]), "r"(b[0]), "r"(b[1]));
}

__device__ __forceinline__ uint32_t ldh_f32(uint32_t addr) {
    float f;
    asm("{\n\t.reg .f16 h;\n\tld.shared.b16 h, [%1];\n\tcvt.f32.f16 %0, h;\n\t}"
        : "=f"(f) : "r"(addr));
    return __float_as_uint(f);
}

#define LDM_X4(r0, r1, r2, r3, addr) \
    asm volatile("ldmatrix.sync.aligned.m8n8.x4.shared.b16 {%0,%1,%2,%3}, [%4];" \
                 : "=r"(r0), "=r"(r1), "=r"(r2), "=r"(r3) : "r"(addr))

#define CP_ASYNC(dst, src) \
    asm volatile("cp.async.cg.shared.global [%0], [%1], 16;" :: "r"(dst), "l"(src))
#define CP_COMMIT() asm volatile("cp.async.commit_group;" ::: "memory")
#define CP_WAIT1()  asm volatile("cp.async.wait_group 1;" ::: "memory")

// ---------------------------------------------------------------------------
// fp16 NT GEMM. Block 128x128, warp 64x32 (8 warps 2x4), BK=64 halves.
// RASTER: m0 = blockIdx.y, n0 = blockIdx.x  (x fastest -> consecutive CTAs
// share the A tile; A becomes L2-resident instead of re-streamed per N-block).
// smem rows [row][k] fp16, stride 144 B. ldmatrix frags. 3-stage cp.async.
// Stage = 36864 B; x3 = 110592 B. 2 CTA/SM.
// ---------------------------------------------------------------------------
#define TGH_STAGE_B  36864
#define TGH_BOFF     18432
#define TGH_SMEM     (3 * TGH_STAGE_B)

template<bool HOUT, bool STATS>
__global__ __launch_bounds__(256, 2)
void hgemm(const __half* __restrict__ A, int lda, long long sA,
           const __half* __restrict__ B, int ldb, long long sB,
           const float* __restrict__ bias,
           void* __restrict__ Cv, int ldC, long long sC,
           int K)
{
    extern __shared__ char smem[];
    const uint32_t sb = smem_u32(smem);

    const int tid  = threadIdx.x;
    const int lane = tid & 31;
    const int wid  = tid >> 5;
    const int wm   = wid & 1;
    const int wn   = wid >> 1;
    const int g    = lane >> 2;
    const int t    = lane & 3;

    A += (long long)blockIdx.z * sA;
    B += (long long)blockIdx.z * sB;
    const long long m0 = (long long)blockIdx.y * 128;   // swapped raster
    const long long n0 = (long long)blockIdx.x * 128;

    // cp.async mapping: s = tid + 256*i -> row = s>>3, c16 = s&7
    const __half* srcA[4];
    const __half* srcB[4];
    uint32_t dstO[4];
    #pragma unroll
    for (int i = 0; i < 4; i++) {
        int s = tid + 256 * i;
        int row = s >> 3, c16 = s & 7;
        srcA[i] = A + (m0 + row) * (long long)lda + c16 * 8;
        srcB[i] = B + (n0 + row) * (long long)ldb + c16 * 8;
        dstO[i] = (uint32_t)(row * 144 + c16 * 16);
    }

    // ldmatrix lane addressing (stride 144 B)
    const int tau = lane >> 3, r8 = lane & 7;
    uint32_t aoff[4], boff[2];
    #pragma unroll
    for (int mt = 0; mt < 4; mt++)
        aoff[mt] = (uint32_t)((wm * 64 + mt * 16 + ((tau & 1) << 3) + r8) * 144
                              + ((tau >> 1) << 4));
    #pragma unroll
    for (int np = 0; np < 2; np++)
        boff[np] = (uint32_t)(TGH_BOFF
                              + (wn * 32 + np * 16 + ((tau >> 1) << 3) + r8) * 144
                              + ((tau & 1) << 4));

    const int NCH = K >> 6;

#define TGH_LOAD(c, st) do {                              \
        uint32_t b_ = sb + (st) * TGH_STAGE_B;            \
        int k_ = (c) << 6;                                \
        _Pragma("unroll")                                 \
        for (int i_ = 0; i_ < 4; i_++) {                  \
            CP_ASYNC(b_ + dstO[i_],            srcA[i_] + k_); \
            CP_ASYNC(b_ + TGH_BOFF + dstO[i_], srcB[i_] + k_); \
        }                                                 \
    } while (0)

    TGH_LOAD(0, 0); CP_COMMIT();
    TGH_LOAD(1, 1); CP_COMMIT();

    float acc[4][4][4];
    #pragma unroll
    for (int a = 0; a < 4; a++)
        #pragma unroll
        for (int b = 0; b < 4; b++)
            #pragma unroll
            for (int q = 0; q < 4; q++) acc[a][b][q] = 0.f;

    for (int c = 0; c < NCH; ++c) {
        const uint32_t base = sb + (c % 3) * TGH_STAGE_B;
        CP_WAIT1();
        __syncthreads();
        if (c + 2 < NCH) { TGH_LOAD(c + 2, (c + 2) % 3); }
        CP_COMMIT();

        #pragma unroll
        for (int kg = 0; kg < 4; kg++) {
            const uint32_t kb = kg * 32;
            uint32_t af[4][4], bf[4][2];
            #pragma unroll
            for (int mt = 0; mt < 4; mt++)
                LDM_X4(af[mt][0], af[mt][1], af[mt][2], af[mt][3],
                       base + aoff[mt] + kb);
            #pragma unroll
            for (int np = 0; np < 2; np++)
                LDM_X4(bf[2 * np][0], bf[2 * np][1], bf[2 * np + 1][0], bf[2 * np + 1][1],
                       base + boff[np] + kb);
            #pragma unroll
            for (int mt = 0; mt < 4; mt++)
                #pragma unroll
                for (int nt = 0; nt < 4; nt++)
                    mma_h(acc[mt][nt], af[mt], bf[nt]);
        }
    }
#undef TGH_LOAD

    // ---- epilogue ----
    float* ssum = nullptr; float* ssq = nullptr;
    if (STATS) {
        __syncthreads();
        ssum = (float*)smem; ssq = ssum + 128;
        if (tid < 128) { ssum[tid] = 0.f; ssq[tid] = 0.f; }
        __syncthreads();
    }

    float colS[4][2], colS2[4][2];
    if (STATS) {
        #pragma unroll
        for (int nt = 0; nt < 4; nt++)
            colS[nt][0] = colS[nt][1] = colS2[nt][0] = colS2[nt][1] = 0.f;
    }

    #pragma unroll
    for (int mt = 0; mt < 4; mt++) {
        const long long row = m0 + wm * 64 + mt * 16 + g;
        #pragma unroll
        for (int nt = 0; nt < 4; nt++) {
            const long long col = n0 + wn * 32 + nt * 8 + 2 * t;
            const float b0 = bias ? __ldg(&bias[col])     : 0.f;
            const float b1 = bias ? __ldg(&bias[col + 1]) : 0.f;
            float v00 = acc[mt][nt][0] + b0, v01 = acc[mt][nt][1] + b1;
            float v10 = acc[mt][nt][2] + b0, v11 = acc[mt][nt][3] + b1;
            if (STATS) {
                colS[nt][0]  += v00 + v10;          colS[nt][1]  += v01 + v11;
                colS2[nt][0] += v00*v00 + v10*v10;  colS2[nt][1] += v01*v01 + v11*v11;
            }
            if (HOUT) {
                __half* Ch = (__half*)Cv + (long long)blockIdx.z * sC;
                *reinterpret_cast<__half2*>(&Ch[row * ldC + col]) =
                    __floats2half2_rn(v00, v01);
                *reinterpret_cast<__half2*>(&Ch[(row + 8) * ldC + col]) =
                    __floats2half2_rn(v10, v11);
            } else {
                float* Cf = (float*)Cv + (long long)blockIdx.z * sC;
                *reinterpret_cast<float2*>(&Cf[row * ldC + col]) = make_float2(v00, v01);
                *reinterpret_cast<float2*>(&Cf[(row + 8) * ldC + col]) = make_float2(v10, v11);
            }
        }
    }

    if (STATS) {
        #pragma unroll
        for (int nt = 0; nt < 4; nt++) {
            const int cl = wn * 32 + nt * 8 + 2 * t;
            atomicAdd(&ssum[cl],     colS[nt][0]);
            atomicAdd(&ssum[cl + 1], colS[nt][1]);
            atomicAdd(&ssq[cl],      colS2[nt][0]);
            atomicAdd(&ssq[cl + 1],  colS2[nt][1]);
        }
        __syncthreads();
        if (tid < 128) {
            atomicAdd(&g_sum[n0 + tid],   ssum[tid]);
            atomicAdd(&g_sumsq[n0 + tid], ssq[tid]);
        }
    }
}

// ---------------------------------------------------------------------------
// phiTg: M_b[i][j] = (1/N) sum_n Phi_b[n][i] * G_b[n][j]
// fp16 smem [k=n][i] stride 272 B; tf32 mma, exact f16->f32 fragments.
// Split-K: 8 chunks of 512 n; BK=16.
// ---------------------------------------------------------------------------
#define PH_STAGE_B 8704
#define PH_SMEM    (3 * PH_STAGE_B)
#define LDP 768

__global__ __launch_bounds__(256, 2)
void phiTg(const __half* __restrict__ P)
{
    extern __shared__ char smem[];
    const uint32_t sb = smem_u32(smem);

    const int tid  = threadIdx.x;
    const int lane = tid & 31;
    const int wid  = tid >> 5;
    const int wm   = wid & 1;
    const int wn   = wid >> 1;
    const int g    = lane >> 2;
    const int t    = lane & 3;

    const int batch = blockIdx.z >> 3;
    const int chunk = blockIdx.z & 7;
    const int i0 = blockIdx.x * 128;
    const int j0 = blockIdx.y * 128;

    const __half* Phi = P + 512;
    const __half* G   = P;
    const long long base = ((long long)batch * Nq + (long long)chunk * 512) * LDP;

    const int nr = tid >> 4, sg = tid & 15;
    const __half* srcP = Phi + base + (long long)nr * LDP + i0 + sg * 8;
    const __half* srcG = G   + base + (long long)nr * LDP + j0 + sg * 8;
    const uint32_t dst = nr * 272 + sg * 16;

    const int NCH = 32;

#define PH_LOAD(c, st) do {                          \
        uint32_t b_ = sb + (st) * PH_STAGE_B;        \
        long long k_ = (long long)(c) * 16 * LDP;    \
        CP_ASYNC(b_ + dst,        srcP + k_);        \
        CP_ASYNC(b_ + 4352 + dst, srcG + k_);        \
    } while (0)

    PH_LOAD(0, 0); CP_COMMIT();
    PH_LOAD(1, 1); CP_COMMIT();

    float acc[4][4][4];
    #pragma unroll
    for (int a = 0; a < 4; a++)
        #pragma unroll
        for (int b = 0; b < 4; b++)
            #pragma unroll
            for (int q = 0; q < 4; q++) acc[a][b][q] = 0.f;

    for (int c = 0; c < NCH; ++c) {
        const int st = c % 3;
        CP_WAIT1();
        __syncthreads();
        if (c + 2 < NCH) { PH_LOAD(c + 2, (c + 2) % 3); }
        CP_COMMIT();

        const uint32_t pA = sb + st * PH_STAGE_B;
        const uint32_t pB = pA + 4352;

        #pragma unroll
        for (int kk = 0; kk < 16; kk += 8) {
            uint32_t af[4][4], bf[4][2];
            #pragma unroll
            for (int mt = 0; mt < 4; mt++) {
                const int ir = wm * 64 + mt * 16 + g;
                af[mt][0] = ldh_f32(pA + ((kk + t) * 136 + ir) * 2);
                af[mt][1] = ldh_f32(pA + ((kk + t) * 136 + ir + 8) * 2);
                af[mt][2] = ldh_f32(pA + ((kk + t + 4) * 136 + ir) * 2);
                af[mt][3] = ldh_f32(pA + ((kk + t + 4) * 136 + ir + 8) * 2);
            }
            #pragma unroll
            for (int nt = 0; nt < 4; nt++) {
                const int jc = wn * 32 + nt * 8 + g;
                bf[nt][0] = ldh_f32(pB + ((kk + t) * 136 + jc) * 2);
                bf[nt][1] = ldh_f32(pB + ((kk + t + 4) * 136 + jc) * 2);
            }
            #pragma unroll
            for (int mt = 0; mt < 4; mt++)
                #pragma unroll
                for (int nt = 0; nt < 4; nt++)
                    mma_t(acc[mt][nt], af[mt], bf[nt]);
        }
    }
#undef PH_LOAD

    float* Mb = g_M + (long long)batch * ICq * ICq;
    const float scale = 1.f / (float)Nq;
    #pragma unroll
    for (int mt = 0; mt < 4; mt++) {
        const int row = i0 + wm * 64 + mt * 16 + g;
        #pragma unroll
        for (int nt = 0; nt < 4; nt++) {
            const int col = j0 + wn * 32 + nt * 8 + 2 * t;
            atomicAdd(&Mb[row * ICq + col],           acc[mt][nt][0] * scale);
            atomicAdd(&Mb[row * ICq + col + 1],       acc[mt][nt][1] * scale);
            atomicAdd(&Mb[(row + 8) * ICq + col],     acc[mt][nt][2] * scale);
            atomicAdd(&Mb[(row + 8) * ICq + col + 1], acc[mt][nt][3] * scale);
        }
    }
}

// ---------------------------------------------------------------------------
// Small kernels
// ---------------------------------------------------------------------------
__global__ __launch_bounds__(256)
void conv_f2h(const float4* __restrict__ src, __half2* __restrict__ dst, int n4)
{
    int i = blockIdx.x * 256 + threadIdx.x;
    if (i < n4) {
        float4 x = src[i];
        dst[2 * i]     = __floats2half2_rn(x.x, x.y);
        dst[2 * i + 1] = __floats2half2_rn(x.z, x.w);
    }
}

__global__ void prep_misc(const float* gb, const float* tb, const float* pb)
{
    int i = blockIdx.x * blockDim.x + threadIdx.x;
    if (i < Bq * ICq * ICq) g_M[i] = 0.f;
    if (i < Cq) { g_sum[i] = 0.f; g_sumsq[i] = 0.f; }
    if (i < ICq) {
        g_bcat[i]       = gb[i];
        g_bcat[i + 256] = tb[i];
        g_bcat[i + 512] = pb[i];
    }
}

// out = (Wy_h - mean)*rsqrt(var+eps)*gamma + beta + v
__global__ __launch_bounds__(256)
void bn_finalize(float* __restrict__ out, const __half2* __restrict__ wy,
                 const float* __restrict__ v,
                 const float* __restrict__ gamma, const float* __restrict__ beta)
{
    const long long i4 = (long long)blockIdx.x * 256 + threadIdx.x;
    const int c4 = (int)(i4 & (Cq / 4 - 1)) * 4;
    float2 a = __half22float2(wy[2 * i4]);
    float2 b = __half22float2(wy[2 * i4 + 1]);
    float4 vv = reinterpret_cast<const float4*>(v)[i4];
    const float inv = 1.f / (float)ROWS;
    float w4[4] = {a.x, a.y, b.x, b.y};
    const float* vp = &vv.x;
    float4 o;
    float* op = &o.x;
    #pragma unroll
    for (int c = 0; c < 4; c++) {
        float mean = g_sum[c4 + c] * inv;
        float var  = g_sumsq[c4 + c] * inv - mean * mean;
        float sc   = gamma[c4 + c] * rsqrtf(var + EPSq);
        op[c] = (w4[c] - mean) * sc + beta[c4 + c] + vp[c];
    }
    reinterpret_cast<float4*>(out)[i4] = o;
}

// ---------------------------------------------------------------------------
// Launch
// ---------------------------------------------------------------------------
extern "C" void kernel_launch(void* const* d_in, const int* in_sizes, int n_in,
                              void* d_out, int out_size)
{
    const float* v     = (const float*)d_in[0];
    const float* g_w   = (const float*)d_in[1];
    const float* g_b   = (const float*)d_in[2];
    const float* th_w  = (const float*)d_in[3];
    const float* th_b  = (const float*)d_in[4];
    const float* ph_w  = (const float*)d_in[5];
    const float* ph_b  = (const float*)d_in[6];
    const float* W_w   = (const float*)d_in[7];
    const float* W_b   = (const float*)d_in[8];
    const float* gamma = (const float*)d_in[9];
    const float* beta  = (const float*)d_in[10];
    float* out = (float*)d_out;

    __half *vh, *Ph, *wh, *Mh, *Qh;
    float *M, *bcat;
    cudaGetSymbolAddress((void**)&vh,   g_vh);
    cudaGetSymbolAddress((void**)&Ph,   g_Ph);
    cudaGetSymbolAddress((void**)&wh,   g_wh);
    cudaGetSymbolAddress((void**)&Mh,   g_Mh);
    cudaGetSymbolAddress((void**)&Qh,   g_Qh);
    cudaGetSymbolAddress((void**)&M,    g_M);
    cudaGetSymbolAddress((void**)&bcat, g_bcat);

    cudaFuncSetAttribute(hgemm<true, false>,
                         cudaFuncAttributeMaxDynamicSharedMemorySize, TGH_SMEM);
    cudaFuncSetAttribute(hgemm<true, true>,
                         cudaFuncAttributeMaxDynamicSharedMemorySize, TGH_SMEM);
    cudaFuncSetAttribute(phiTg,
                         cudaFuncAttributeMaxDynamicSharedMemorySize, PH_SMEM);

    const int WK = ICq * Cq;

    prep_misc<<<(Bq * ICq * ICq + 255) / 256, 256>>>(g_b, th_b, ph_b);

    conv_f2h<<<(ROWS * Cq / 4 + 255) / 256, 256>>>((const float4*)v, (__half2*)vh, ROWS * Cq / 4);
    conv_f2h<<<(WK / 4 + 255) / 256, 256>>>((const float4*)g_w,  (__half2*)(wh + 0 * WK), WK / 4);
    conv_f2h<<<(WK / 4 + 255) / 256, 256>>>((const float4*)th_w, (__half2*)(wh + 1 * WK), WK / 4);
    conv_f2h<<<(WK / 4 + 255) / 256, 256>>>((const float4*)ph_w, (__half2*)(wh + 2 * WK), WK / 4);
    conv_f2h<<<(WK / 4 + 255) / 256, 256>>>((const float4*)W_w,  (__half2*)(wh + 3 * WK), WK / 4);

    // 1. Fused projections: P = vh @ [g;th;ph]^T + bcat  (32768 x 768, K=1024)
    //    grid = (N-tiles, M-tiles): x-fastest shares the A (vh) tile in L2.
    {
        dim3 grid(768 / 128, ROWS / 128, 1);     // (6, 256)
        hgemm<true, false><<<grid, 256, TGH_SMEM>>>(
            vh, Cq, 0LL, wh, Cq, 0LL, bcat, Ph, 768, 0LL, Cq);
    }

    // 2. M_b = Phi_b^T G_b / N, convert to fp16
    {
        dim3 grid(ICq / 128, ICq / 128, Bq * 8);
        phiTg<<<grid, 256, PH_SMEM>>>(Ph);
        conv_f2h<<<(Bq * ICq * ICq / 4 + 255) / 256, 256>>>(
            (const float4*)M, (__half2*)Mh, Bq * ICq * ICq / 4);
    }

    // 3. Q_b = W_w @ M_b^T  (1024 x 256, K=256)
    {
        dim3 grid(ICq / 128, Cq / 128, Bq);      // (2, 8, 8)
        hgemm<true, false><<<grid, 256, TGH_SMEM>>>(
            wh + 3 * WK, ICq, 0LL,
            Mh, ICq, (long long)ICq * ICq,
            nullptr,
            Qh, ICq, (long long)Cq * ICq,
            ICq);
    }

    // 4. W_y = Theta_b @ Q_b^T + W_b  (fp16 out into vh) + BN stats
    {
        dim3 grid(Cq / 128, Nq / 128, Bq);       // (8, 32, 8)
        hgemm<true, true><<<grid, 256, TGH_SMEM>>>(
            Ph + 256, 768, (long long)Nq * 768,
            Qh, ICq, (long long)Cq * ICq,
            W_b,
            vh, Cq, (long long)Nq * Cq,
            ICq);
    }

    // 5. normalize + residual (reads fp16 W_y + fp32 v)
    bn_finalize<<<(ROWS * Cq / 4) / 256, 256>>>(
        out, (const __half2*)vh, v, gamma, beta);
}